// round 4
// baseline (speedup 1.0000x reference)
#include <cuda_runtime.h>
#include <math.h>

// Problem constants (fixed shapes from setup_inputs)
#define BB   32
#define CC   256
#define NN   64
#define NSQ  4096          // N*N
#define PP   2080          // N*(N+1)/2 (triu incl diagonal)
#define SS   64
#define BP   66560         // BB*PP
#define SBP  4259840       // SS*BP

typedef unsigned long long u64;

// ---------------- scratch (static device allocations are allowed) -----------
__device__ int   g_flat[PP];       // p -> flattened N*N index (triu order)
__device__ int   g_scatter[SS];    // sentence -> video index
__device__ float g_sf[CC * SS];    // normalized sentences, layout [c][s]
__device__ float g_G[SBP];         // G[s][b*P+p] = sf_norm[s] . raw_video[b,:,p]  (17MB)
__device__ float g_norm[BP];       // ||video[b,:,p]||  per proposal
__device__ int   g_col[SS];        // scatter[s]*P + argmax_p iou[s,p]
__device__ float g_qsum[SS];       // inter-query neg-exp sums

// ---------------- f32x2 helpers (FFMA2: full-rate fp32 path) ----------------
__device__ __forceinline__ u64 dup_f32(float v) {
    u64 r; unsigned int u = __float_as_uint(v);
    asm("mov.b64 %0, {%1, %1};" : "=l"(r) : "r"(u));
    return r;
}
__device__ __forceinline__ void ffma2(u64& acc, u64 a, u64 b) {
    asm("fma.rn.f32x2 %0, %1, %2, %0;" : "+l"(acc) : "l"(a), "l"(b));
}
__device__ __forceinline__ float2 u2f2(u64 a) {
    float2 f;
    f.x = __uint_as_float((unsigned int)(a & 0xffffffffULL));
    f.y = __uint_as_float((unsigned int)(a >> 32));
    return f;
}

// ---------------- kernel 0: triu index table --------------------------------
__global__ void init_idx_kernel() {
    int p = blockIdx.x * blockDim.x + threadIdx.x;
    if (p >= PP) return;
    int start = 0, row = 0, col = 0;
    for (int i = 0; i < NN; i++) {
        int len = NN - i;
        if (p < start + len) { row = i; col = i + (p - start); break; }
        start += len;
    }
    g_flat[p] = row * NN + col;
}

// ---------------- kernel 1: normalize sentences, scatter, zero qsum ---------
__global__ void setup_kernel(const float* __restrict__ sents,
                             const int* __restrict__ num_targets) {
    int s = blockIdx.x;        // 0..63
    int t = threadIdx.x;       // 0..255 == channel
    __shared__ float red[256];
    float v = sents[s * CC + t];
    red[t] = v * v;
    __syncthreads();
    for (int off = 128; off > 0; off >>= 1) {
        if (t < off) red[t] += red[t + off];
        __syncthreads();
    }
    __shared__ float inv;
    if (t == 0) inv = 1.0f / fmaxf(sqrtf(red[0]), 1e-12f);
    __syncthreads();
    g_sf[t * SS + s] = v * inv;           // [c][s] layout for the GEMM
    if (s == 0 && t < SS) g_qsum[t] = 0.0f;
    if (s == 0 && t == 0) {
        int idx = 0;
        for (int b = 0; b < BB && idx < SS; b++) {
            int n = num_targets[b];
            for (int k = 0; k < n && idx < SS; k++) g_scatter[idx++] = b;
        }
    }
}

// ---------------- kernel 2: main GEMM + norms -------------------------------
// grid (65, 32): block = (video b, 32-proposal tile). 256 threads.
// thread tile: 4 s (2 packed pairs) x 2 p  -> 4 packed accumulators.
__global__ __launch_bounds__(256) void gemm_kernel(const float* __restrict__ video) {
    const int tid = threadIdx.x;
    const int b  = blockIdx.y;
    const int pb = blockIdx.x * 32;

    __shared__ float vt[16][32];     // video chunk [c][p]
    __shared__ float sfc[16][64];    // sentence chunk [c][s]
    __shared__ int   fidx[32];
    __shared__ float nsm[32];

    if (tid < 32) { fidx[tid] = g_flat[pb + tid]; nsm[tid] = 0.0f; }
    __syncthreads();

    const int ts4 = (tid >> 4) * 4;   // s base (0..60)
    const int tp2 = (tid & 15) * 2;   // p base within tile (0..30)
    const int myp = tid & 31;

    u64 a00 = 0, a01 = 0, a10 = 0, a11 = 0;
    float nacc = 0.0f;

    const float* vbase = video + (size_t)b * CC * NSQ;
    const int e1c = tid >> 5, e1p = tid & 31;          // element tid
    const int e2c = e1c + 8;                           // element tid+256 (same p)

    for (int cc = 0; cc < 16; ++cc) {
        const int c0 = cc * 16;
        // stage video chunk (512 floats) + accumulate squared norm
        float x0 = vbase[(size_t)(c0 + e1c) * NSQ + fidx[e1p]];
        float x1 = vbase[(size_t)(c0 + e2c) * NSQ + fidx[e1p]];
        vt[e1c][e1p] = x0;
        vt[e2c][e1p] = x1;
        nacc += x0 * x0 + x1 * x1;
        // stage sentence chunk (1024 floats), float4 per thread
        {
            int e = tid * 4;
            int c = e >> 6, s = e & 63;
            *reinterpret_cast<float4*>(&sfc[c][s]) =
                *reinterpret_cast<const float4*>(&g_sf[(c0 + c) * SS + s]);
        }
        __syncthreads();
        #pragma unroll
        for (int ci = 0; ci < 16; ++ci) {
            float2 vv = *reinterpret_cast<const float2*>(&vt[ci][tp2]);
            u64 v0 = dup_f32(vv.x);
            u64 v1 = dup_f32(vv.y);
            ulonglong2 sp = *reinterpret_cast<const ulonglong2*>(&sfc[ci][ts4]);
            ffma2(a00, sp.x, v0);
            ffma2(a01, sp.x, v1);
            ffma2(a10, sp.y, v0);
            ffma2(a11, sp.y, v1);
        }
        __syncthreads();
    }

    atomicAdd(&nsm[myp], nacc);

    const size_t colbase = (size_t)b * PP + pb + tp2;
    float2 f00 = u2f2(a00), f01 = u2f2(a01), f10 = u2f2(a10), f11 = u2f2(a11);
    *reinterpret_cast<float2*>(&g_G[(size_t)(ts4 + 0) * BP + colbase]) = make_float2(f00.x, f01.x);
    *reinterpret_cast<float2*>(&g_G[(size_t)(ts4 + 1) * BP + colbase]) = make_float2(f00.y, f01.y);
    *reinterpret_cast<float2*>(&g_G[(size_t)(ts4 + 2) * BP + colbase]) = make_float2(f10.x, f11.x);
    *reinterpret_cast<float2*>(&g_G[(size_t)(ts4 + 3) * BP + colbase]) = make_float2(f10.y, f11.y);

    __syncthreads();
    if (tid < 32) g_norm[b * PP + pb + tid] = fmaxf(sqrtf(nsm[tid]), 1e-12f);
}

// ---------------- kernel 3: per-sentence argmax of iou (topk, K=1) ----------
__global__ void topk_kernel(const float* __restrict__ iou) {
    int s = blockIdx.x, t = threadIdx.x;
    float best = -1e30f; int bi = 0x3fffffff;
    for (int p = t; p < PP; p += 256) {
        float v = iou[s * NSQ + g_flat[p]];
        if (v > best) { best = v; bi = p; }     // increasing p -> first max kept
    }
    __shared__ float bv[256]; __shared__ int bix[256];
    bv[t] = best; bix[t] = bi;
    __syncthreads();
    for (int off = 128; off > 0; off >>= 1) {
        if (t < off) {
            if (bv[t + off] > bv[t] ||
                (bv[t + off] == bv[t] && bix[t + off] < bix[t])) {
                bv[t] = bv[t + off]; bix[t] = bix[t + off];
            }
        }
        __syncthreads();
    }
    if (t == 0) g_col[s] = g_scatter[s] * PP + bix[0];
}

// ---------------- kernel 4: inter-query masked neg-exp sum ------------------
// grid (8, 64): x = column chunk (8320 cols), y = sentence.
__global__ __launch_bounds__(256) void qsum_kernel(const float* __restrict__ iou) {
    const int s = blockIdx.y;
    const int scat = g_scatter[s];
    const int start = blockIdx.x * (BP / 8);
    const int end = start + (BP / 8);
    const float* Gs = g_G + (size_t)s * BP;
    float acc = 0.0f;
    for (int col = start + threadIdx.x; col < end; col += 256) {
        float val = Gs[col] / g_norm[col];
        int b = col / PP;
        bool neg = true;
        if (b == scat) {
            int p = col - b * PP;
            if (iou[s * NSQ + g_flat[p]] > 0.5f) neg = false;
        }
        if (neg) acc += expf(val * 10.0f);    // / T_Q, T_Q = 0.1
    }
    __shared__ float r[256];
    r[threadIdx.x] = acc;
    __syncthreads();
    for (int off = 128; off > 0; off >>= 1) {
        if (threadIdx.x < off) r[threadIdx.x] += r[threadIdx.x + off];
        __syncthreads();
    }
    if (threadIdx.x == 0) atomicAdd(&g_qsum[s], r[0]);
}

// ---------------- kernel 5: assemble both losses ----------------------------
__global__ void final_kernel(float* __restrict__ out) {
    int s = threadIdx.x;   // 64 threads
    int col = g_col[s];
    float inv = 1.0f / g_norm[col];
    float pos = g_G[(size_t)s * BP + col] * inv;
    // inter-video: topk_video[s] . sf[t] = G[t][col_s]/norm
    float nv = 0.0f;
    for (int t2 = 0; t2 < SS; t2++) {
        if (t2 != s) nv += expf(g_G[(size_t)t2 * BP + col] * inv * 10.0f);  // / T_V
    }
    float pe = expf(pos * 10.0f);
    float lv = -(pos * 10.0f - logf(pe + nv));
    float lq = -(pos * 10.0f - logf(pe + g_qsum[s]));
    __shared__ float sv[64], sq[64];
    sv[s] = lv; sq[s] = lq;
    __syncthreads();
    for (int off = 32; off > 0; off >>= 1) {
        if (s < off) { sv[s] += sv[s + off]; sq[s] += sq[s + off]; }
        __syncthreads();
    }
    if (s == 0) {
        out[0] = sv[0] * (1.0f / SS);
        out[1] = sq[0] * (1.0f / SS);
    }
}

// ---------------- launch ----------------------------------------------------
extern "C" void kernel_launch(void* const* d_in, const int* in_sizes, int n_in,
                              void* d_out, int out_size) {
    (void)in_sizes; (void)n_in; (void)out_size;
    const float* video = (const float*)d_in[0];   // [B,C,N,N] f32
    const float* sents = (const float*)d_in[1];   // [S,C] f32
    const int*   ntgt  = (const int*)d_in[2];     // [B] i32
    const float* iou   = (const float*)d_in[3];   // [S,N,N] f32
    // d_in[4] = mask2d (structural triu, hardcoded)
    float* out = (float*)d_out;

    init_idx_kernel<<<(PP + 255) / 256, 256>>>();
    setup_kernel<<<SS, 256>>>(sents, ntgt);
    gemm_kernel<<<dim3(PP / 32, BB), 256>>>(video);
    topk_kernel<<<SS, 256>>>(iou);
    qsum_kernel<<<dim3(8, SS), 256>>>(iou);
    final_kernel<<<1, SS>>>(out);
}

// round 8
// speedup vs baseline: 1.2179x; 1.2179x over previous
#include <cuda_runtime.h>
#include <math.h>

// Fixed problem shapes
#define BB   32
#define CC   256
#define NN   64
#define NSQ  4096          // N*N
#define PP   2080          // N*(N+1)/2 triu count
#define SS   64
#define BP   66560         // BB*PP
#define LOG2E10 14.4269504089f   // 10 / T * log2(e), T = 0.1
#define LN2     0.69314718056f

typedef unsigned long long u64;

// ---------------- scratch ----------------------------------------------------
__device__ int   g_flat[PP];            // p -> flattened N*N index
__device__ int   g_scatter[SS];         // sentence -> video index
__device__ float g_sf[CC * SS];         // normalized sentences [c][s]
__device__ float g_G[(size_t)SS * BP];  // raw dot products  [s][b*P+p]
__device__ float g_rnormC[BP];          // (1/||v||) * 10*log2e per column
__device__ u64   g_best[SS];            // packed (iou_bits, ~p) argmax
__device__ float g_qpart[SS * BB];      // per-(s,b) neg-exp partial sums

// ---------------- fast exp2 (no MUFU): 2^t, |err| ~ 2e-6 --------------------
__device__ __forceinline__ float fexp2(float t) {
    float z = t + 12582912.0f;                       // 1.5*2^23, RN to int
    int   i = __float_as_int(z) - 0x4B400000;        // integer part
    float r = t - (z - 12582912.0f);                 // r in [-0.5, 0.5]
    float p = 0.00133335581f;
    p = fmaf(p, r, 0.00961812910f);
    p = fmaf(p, r, 0.05550410866f);
    p = fmaf(p, r, 0.24022650696f);
    p = fmaf(p, r, 0.69314718056f);
    p = fmaf(p, r, 1.0f);
    return __int_as_float(__float_as_int(p) + (i << 23));
}

// ---------------- f32x2 helpers (FFMA2 full-rate fp32) ----------------------
__device__ __forceinline__ u64 dup_f32(float v) {
    u64 r; unsigned int u = __float_as_uint(v);
    asm("mov.b64 %0, {%1, %1};" : "=l"(r) : "r"(u));
    return r;
}
__device__ __forceinline__ void ffma2(u64& acc, u64 a, u64 b) {
    asm("fma.rn.f32x2 %0, %1, %2, %0;" : "+l"(acc) : "l"(a), "l"(b));
}
__device__ __forceinline__ float2 u2f2(u64 a) {
    float2 f;
    f.x = __uint_as_float((unsigned int)(a & 0xffffffffULL));
    f.y = __uint_as_float((unsigned int)(a >> 32));
    return f;
}

// ---------------- kernel 1: setup (flat idx, sf normalize, scatter, init) ---
__global__ void setup_kernel(const float* __restrict__ sents,
                             const int* __restrict__ num_targets) {
    const int s = blockIdx.x;        // 0..63
    const int t = threadIdx.x;       // 0..255 == channel
    const int u = s * 256 + t;

    if (u < PP) {                    // triu index table
        int start = 0, row = 0, col = 0;
        for (int i = 0; i < NN; i++) {
            int len = NN - i;
            if (u < start + len) { row = i; col = i + (u - start); break; }
            start += len;
        }
        g_flat[u] = row * NN + col;
    }
    if (u < SS) g_best[u] = 0ULL;
    if (u == 0) {
        int idx = 0;
        for (int b = 0; b < BB && idx < SS; b++) {
            int n = num_targets[b];
            for (int k = 0; k < n && idx < SS; k++) g_scatter[idx++] = b;
        }
    }

    __shared__ float red[256];
    float v = sents[s * CC + t];
    red[t] = v * v;
    __syncthreads();
    for (int off = 128; off > 0; off >>= 1) {
        if (t < off) red[t] += red[t + off];
        __syncthreads();
    }
    __shared__ float inv;
    if (t == 0) inv = 1.0f / fmaxf(sqrtf(red[0]), 1e-12f);
    __syncthreads();
    g_sf[t * SS + s] = v * inv;      // [c][s] layout for GEMM
}

// ---------------- kernel 2: main GEMM + norms (double-buffered) -------------
// grid (65, 32): (32-proposal tile, video b). 256 threads.
// thread tile: 4 s (2 packed f32x2 pairs) x 2 p.
__global__ __launch_bounds__(256) void gemm_kernel(const float* __restrict__ video) {
    const int tid = threadIdx.x;
    const int b  = blockIdx.y;
    const int pb = blockIdx.x * 32;

    __shared__ float vt[2][16][32];
    __shared__ float sfc[2][16][64];
    __shared__ int   fidx[32];
    __shared__ float nred[8][32];

    if (tid < 32) fidx[tid] = g_flat[pb + tid];
    __syncthreads();

    const int e1c  = tid >> 5, e1p = tid & 31;          // video staging coords
    const int sc_c = (tid * 4) >> 6, sc_s = (tid * 4) & 63;
    const int ts4  = (tid >> 4) * 4;                    // s base
    const int tp2  = (tid & 15) * 2;                    // p base

    const float* vbase = video + (size_t)b * CC * NSQ;
    const int myflat = fidx[e1p];

    // preload chunk 0
    float x0 = vbase[(size_t)e1c * NSQ + myflat];
    float x1 = vbase[(size_t)(e1c + 8) * NSQ + myflat];
    float4 sfr = *reinterpret_cast<const float4*>(&g_sf[sc_c * SS + sc_s]);

    float nacc = x0 * x0 + x1 * x1;
    vt[0][e1c][e1p] = x0; vt[0][e1c + 8][e1p] = x1;
    *reinterpret_cast<float4*>(&sfc[0][sc_c][sc_s]) = sfr;

    u64 a00 = 0, a01 = 0, a10 = 0, a11 = 0;
    int cur = 0;
    __syncthreads();

    for (int cc = 0; cc < 16; ++cc) {
        if (cc < 15) {                       // prefetch next chunk into regs
            const int c0 = (cc + 1) * 16;
            x0  = vbase[(size_t)(c0 + e1c) * NSQ + myflat];
            x1  = vbase[(size_t)(c0 + e1c + 8) * NSQ + myflat];
            sfr = *reinterpret_cast<const float4*>(&g_sf[(c0 + sc_c) * SS + sc_s]);
        }
        #pragma unroll
        for (int ci = 0; ci < 16; ++ci) {
            float2 vv = *reinterpret_cast<const float2*>(&vt[cur][ci][tp2]);
            u64 v0 = dup_f32(vv.x);
            u64 v1 = dup_f32(vv.y);
            ulonglong2 sp = *reinterpret_cast<const ulonglong2*>(&sfc[cur][ci][ts4]);
            ffma2(a00, sp.x, v0);
            ffma2(a01, sp.x, v1);
            ffma2(a10, sp.y, v0);
            ffma2(a11, sp.y, v1);
        }
        if (cc < 15) {                       // stage next chunk to other buffer
            cur ^= 1;
            nacc += x0 * x0 + x1 * x1;
            vt[cur][e1c][e1p] = x0; vt[cur][e1c + 8][e1p] = x1;
            *reinterpret_cast<float4*>(&sfc[cur][sc_c][sc_s]) = sfr;
            __syncthreads();
        }
    }

    // outputs
    const size_t colbase = (size_t)b * PP + pb + tp2;
    float2 f00 = u2f2(a00), f01 = u2f2(a01), f10 = u2f2(a10), f11 = u2f2(a11);
    *reinterpret_cast<float2*>(&g_G[(size_t)(ts4 + 0) * BP + colbase]) = make_float2(f00.x, f01.x);
    *reinterpret_cast<float2*>(&g_G[(size_t)(ts4 + 1) * BP + colbase]) = make_float2(f00.y, f01.y);
    *reinterpret_cast<float2*>(&g_G[(size_t)(ts4 + 2) * BP + colbase]) = make_float2(f10.x, f11.x);
    *reinterpret_cast<float2*>(&g_G[(size_t)(ts4 + 3) * BP + colbase]) = make_float2(f10.y, f11.y);

    // deterministic norm reduction (8 partials per p, fixed order)
    nred[e1c][e1p] = nacc;
    __syncthreads();
    if (tid < 32) {
        float sum = 0.0f;
        #pragma unroll
        for (int k = 0; k < 8; k++) sum += nred[k][tid];
        g_rnormC[b * PP + pb + tid] = rsqrtf(sum) * LOG2E10;
    }
}

// ---------------- kernel 3: argmax of iou via packed atomicMax --------------
// grid (4, 64): 4 chunks of 520 proposals x 64 sentences.
__global__ __launch_bounds__(256) void topk_kernel(const float* __restrict__ iou) {
    const int s = blockIdx.y;
    const int base = blockIdx.x * (PP / 4);
    const float* ious = iou + s * NSQ;
    u64 best = 0ULL;
    for (int p = base + threadIdx.x; p < base + PP / 4; p += 256) {
        float v = ious[g_flat[p]];
        u64 key = ((u64)__float_as_uint(v) << 32) | (u64)(0xFFFFFFFFu - (unsigned)p);
        best = best > key ? best : key;
    }
    __shared__ u64 r[256];
    r[threadIdx.x] = best;
    __syncthreads();
    for (int off = 128; off > 0; off >>= 1) {
        if (threadIdx.x < off && r[threadIdx.x + off] > r[threadIdx.x])
            r[threadIdx.x] = r[threadIdx.x + off];
        __syncthreads();
    }
    if (threadIdx.x == 0) atomicMax(&g_best[s], r[0]);
}

// ---------------- kernel 4: inter-query masked neg-exp partials -------------
// grid (32, 64): one block per (video b, sentence s).
__global__ __launch_bounds__(256) void qsum_kernel(const float* __restrict__ iou) {
    const int b = blockIdx.x, s = blockIdx.y;
    const bool isscat = (g_scatter[s] == b);
    const float4* G4 = reinterpret_cast<const float4*>(g_G + (size_t)s * BP + b * PP);
    const float4* R4 = reinterpret_cast<const float4*>(g_rnormC + b * PP);
    const int4*   F4 = reinterpret_cast<const int4*>(g_flat);
    const float* ious = iou + s * NSQ;

    float acc = 0.0f;
    for (int i = threadIdx.x; i < PP / 4; i += 256) {
        float4 g = G4[i], rn = R4[i];
        float e0 = fexp2(g.x * rn.x);
        float e1 = fexp2(g.y * rn.y);
        float e2 = fexp2(g.z * rn.z);
        float e3 = fexp2(g.w * rn.w);
        if (isscat) {
            int4 f = F4[i];
            if (ious[f.x] > 0.5f) e0 = 0.0f;
            if (ious[f.y] > 0.5f) e1 = 0.0f;
            if (ious[f.z] > 0.5f) e2 = 0.0f;
            if (ious[f.w] > 0.5f) e3 = 0.0f;
        }
        acc += (e0 + e1) + (e2 + e3);
    }
    __shared__ float r[256];
    r[threadIdx.x] = acc;
    __syncthreads();
    for (int off = 128; off > 0; off >>= 1) {
        if (threadIdx.x < off) r[threadIdx.x] += r[threadIdx.x + off];
        __syncthreads();
    }
    if (threadIdx.x == 0) g_qpart[s * BB + b] = r[0];
}

// ---------------- kernel 5: assemble both losses ----------------------------
__global__ void final_kernel(float* __restrict__ out) {
    const int s = threadIdx.x;   // 64 threads
    const int p = (int)(0xFFFFFFFFu - (unsigned)(g_best[s] & 0xFFFFFFFFull));
    const int col = g_scatter[s] * PP + p;
    const float rn = g_rnormC[col];

    const float tpos  = g_G[(size_t)s * BP + col] * rn;   // pos/T * log2e
    const float pos10 = tpos * LN2;                       // pos/T
    const float pe    = fexp2(tpos);

    float nv = 0.0f;                                      // inter-video negs
    for (int t2 = 0; t2 < SS; t2++)
        if (t2 != s) nv += fexp2(g_G[(size_t)t2 * BP + col] * rn);

    float qs = 0.0f;                                      // inter-query negs
    #pragma unroll
    for (int b = 0; b < BB; b++) qs += g_qpart[s * BB + b];

    const float lv = logf(pe + nv) - pos10;
    const float lq = logf(pe + qs) - pos10;

    __shared__ float sv[64], sq[64];
    sv[s] = lv; sq[s] = lq;
    __syncthreads();
    for (int off = 32; off > 0; off >>= 1) {
        if (s < off) { sv[s] += sv[s + off]; sq[s] += sq[s + off]; }
        __syncthreads();
    }
    if (s == 0) {
        out[0] = sv[0] * (1.0f / SS);
        out[1] = sq[0] * (1.0f / SS);
    }
}

// ---------------- launch ----------------------------------------------------
extern "C" void kernel_launch(void* const* d_in, const int* in_sizes, int n_in,
                              void* d_out, int out_size) {
    (void)in_sizes; (void)n_in; (void)out_size;
    const float* video = (const float*)d_in[0];   // [B,C,N,N] f32
    const float* sents = (const float*)d_in[1];   // [S,C] f32
    const int*   ntgt  = (const int*)d_in[2];     // [B] i32
    const float* iou   = (const float*)d_in[3];   // [S,N,N] f32
    // d_in[4] = mask2d (structural triu, hardcoded)
    float* out = (float*)d_out;

    setup_kernel<<<SS, 256>>>(sents, ntgt);
    gemm_kernel<<<dim3(PP / 32, BB), 256>>>(video);
    topk_kernel<<<dim3(4, SS), 256>>>(iou);
    qsum_kernel<<<dim3(BB, SS), 256>>>(iou);
    final_kernel<<<1, SS>>>(out);
}

// round 12
// speedup vs baseline: 1.2246x; 1.0055x over previous
#include <cuda_runtime.h>
#include <math.h>

// Fixed problem shapes
#define BB   32
#define CC   256
#define NN   64
#define NSQ  4096          // N*N
#define PP   2080          // N*(N+1)/2 triu count
#define SS   64
#define BP   66560         // BB*PP
#define LOG2E10 14.4269504089f   // 10 / T * log2(e), T = 0.1
#define LN2     0.69314718056f

typedef unsigned long long u64;

// ---------------- scratch ----------------------------------------------------
__device__ int   g_flat[PP];            // p -> flattened N*N index
__device__ int   g_scatter[SS];         // sentence -> video index
__device__ float g_sf[CC * SS];         // normalized sentences [c][s]
__device__ float g_G[(size_t)SS * BP];  // raw dot products  [s][b*P+p]
__device__ float g_rnormC[BP];          // (1/||v||) * 10*log2e per column
__device__ u64   g_best[SS];            // packed (iou_bits, ~p) argmax
__device__ float g_qpart[SS * BB];      // per-(s,b) neg-exp partial sums

// ---------------- fast exp2 (no MUFU): 2^t, |err| ~ 2e-6 --------------------
__device__ __forceinline__ float fexp2(float t) {
    float z = t + 12582912.0f;                       // 1.5*2^23, RN to int
    int   i = __float_as_int(z) - 0x4B400000;        // integer part
    float r = t - (z - 12582912.0f);                 // r in [-0.5, 0.5]
    float p = 0.00133335581f;
    p = fmaf(p, r, 0.00961812910f);
    p = fmaf(p, r, 0.05550410866f);
    p = fmaf(p, r, 0.24022650696f);
    p = fmaf(p, r, 0.69314718056f);
    p = fmaf(p, r, 1.0f);
    return __int_as_float(__float_as_int(p) + (i << 23));
}

// ---------------- f32x2 helpers (FFMA2 full-rate fp32) ----------------------
__device__ __forceinline__ u64 dup_f32(float v) {
    u64 r; unsigned int u = __float_as_uint(v);
    asm("mov.b64 %0, {%1, %1};" : "=l"(r) : "r"(u));
    return r;
}
__device__ __forceinline__ void ffma2(u64& acc, u64 a, u64 b) {
    asm("fma.rn.f32x2 %0, %1, %2, %0;" : "+l"(acc) : "l"(a), "l"(b));
}
__device__ __forceinline__ float2 u2f2(u64 a) {
    float2 f;
    f.x = __uint_as_float((unsigned int)(a & 0xffffffffULL));
    f.y = __uint_as_float((unsigned int)(a >> 32));
    return f;
}

// ---------------- kernel 1: setup (flat idx, sf normalize, scatter, init) ---
__global__ void setup_kernel(const float* __restrict__ sents,
                             const int* __restrict__ num_targets) {
    const int s = blockIdx.x;        // 0..63
    const int t = threadIdx.x;       // 0..255 == channel
    const int u = s * 256 + t;

    if (u < PP) {                    // triu index table
        int start = 0, row = 0, col = 0;
        for (int i = 0; i < NN; i++) {
            int len = NN - i;
            if (u < start + len) { row = i; col = i + (u - start); break; }
            start += len;
        }
        g_flat[u] = row * NN + col;
    }
    if (u < SS) g_best[u] = 0ULL;
    if (u == 0) {
        int idx = 0;
        for (int b = 0; b < BB && idx < SS; b++) {
            int n = num_targets[b];
            for (int k = 0; k < n && idx < SS; k++) g_scatter[idx++] = b;
        }
    }

    __shared__ float red[256];
    float v = sents[s * CC + t];
    red[t] = v * v;
    __syncthreads();
    for (int off = 128; off > 0; off >>= 1) {
        if (t < off) red[t] += red[t + off];
        __syncthreads();
    }
    __shared__ float inv;
    if (t == 0) inv = 1.0f / fmaxf(sqrtf(red[0]), 1e-12f);
    __syncthreads();
    g_sf[t * SS + s] = v * inv;      // [c][s] layout for GEMM
}

// ---------------- kernel 2: main GEMM + norms (double-buffered) -------------
// grid (65, 32): (32-proposal tile, video b). 256 threads.
// thread tile: 4 s (2 packed f32x2 pairs) x 2 p.
__global__ __launch_bounds__(256) void gemm_kernel(const float* __restrict__ video) {
    const int tid = threadIdx.x;
    const int b  = blockIdx.y;
    const int pb = blockIdx.x * 32;

    __shared__ float vt[2][16][32];
    __shared__ float sfc[2][16][64];
    __shared__ int   fidx[32];
    __shared__ float nred[8][32];

    if (tid < 32) fidx[tid] = g_flat[pb + tid];
    __syncthreads();

    const int e1c  = tid >> 5, e1p = tid & 31;          // video staging coords
    const int sc_c = (tid * 4) >> 6, sc_s = (tid * 4) & 63;
    const int ts4  = (tid >> 4) * 4;                    // s base
    const int tp2  = (tid & 15) * 2;                    // p base

    const float* vbase = video + (size_t)b * CC * NSQ;
    const int myflat = fidx[e1p];

    // preload chunk 0
    float x0 = vbase[(size_t)e1c * NSQ + myflat];
    float x1 = vbase[(size_t)(e1c + 8) * NSQ + myflat];
    float4 sfr = *reinterpret_cast<const float4*>(&g_sf[sc_c * SS + sc_s]);

    float nacc = x0 * x0 + x1 * x1;
    vt[0][e1c][e1p] = x0; vt[0][e1c + 8][e1p] = x1;
    *reinterpret_cast<float4*>(&sfc[0][sc_c][sc_s]) = sfr;

    u64 a00 = 0, a01 = 0, a10 = 0, a11 = 0;
    int cur = 0;
    __syncthreads();

    for (int cc = 0; cc < 16; ++cc) {
        if (cc < 15) {                       // prefetch next chunk into regs
            const int c0 = (cc + 1) * 16;
            x0  = vbase[(size_t)(c0 + e1c) * NSQ + myflat];
            x1  = vbase[(size_t)(c0 + e1c + 8) * NSQ + myflat];
            sfr = *reinterpret_cast<const float4*>(&g_sf[(c0 + sc_c) * SS + sc_s]);
        }
        #pragma unroll
        for (int ci = 0; ci < 16; ++ci) {
            float2 vv = *reinterpret_cast<const float2*>(&vt[cur][ci][tp2]);
            u64 v0 = dup_f32(vv.x);
            u64 v1 = dup_f32(vv.y);
            ulonglong2 sp = *reinterpret_cast<const ulonglong2*>(&sfc[cur][ci][ts4]);
            ffma2(a00, sp.x, v0);
            ffma2(a01, sp.x, v1);
            ffma2(a10, sp.y, v0);
            ffma2(a11, sp.y, v1);
        }
        if (cc < 15) {                       // stage next chunk to other buffer
            cur ^= 1;
            nacc += x0 * x0 + x1 * x1;
            vt[cur][e1c][e1p] = x0; vt[cur][e1c + 8][e1p] = x1;
            *reinterpret_cast<float4*>(&sfc[cur][sc_c][sc_s]) = sfr;
            __syncthreads();
        }
    }

    // outputs
    const size_t colbase = (size_t)b * PP + pb + tp2;
    float2 f00 = u2f2(a00), f01 = u2f2(a01), f10 = u2f2(a10), f11 = u2f2(a11);
    *reinterpret_cast<float2*>(&g_G[(size_t)(ts4 + 0) * BP + colbase]) = make_float2(f00.x, f01.x);
    *reinterpret_cast<float2*>(&g_G[(size_t)(ts4 + 1) * BP + colbase]) = make_float2(f00.y, f01.y);
    *reinterpret_cast<float2*>(&g_G[(size_t)(ts4 + 2) * BP + colbase]) = make_float2(f10.x, f11.x);
    *reinterpret_cast<float2*>(&g_G[(size_t)(ts4 + 3) * BP + colbase]) = make_float2(f10.y, f11.y);

    // deterministic norm reduction (8 partials per p, fixed order)
    nred[e1c][e1p] = nacc;
    __syncthreads();
    if (tid < 32) {
        float sum = 0.0f;
        #pragma unroll
        for (int k = 0; k < 8; k++) sum += nred[k][tid];
        g_rnormC[b * PP + pb + tid] = rsqrtf(sum) * LOG2E10;
    }
}

// ---------------- kernel 3: argmax of iou via packed atomicMax --------------
// grid (4, 64): 4 chunks of 520 proposals x 64 sentences.
__global__ __launch_bounds__(256) void topk_kernel(const float* __restrict__ iou) {
    const int s = blockIdx.y;
    const int base = blockIdx.x * (PP / 4);
    const float* ious = iou + s * NSQ;
    u64 best = 0ULL;
    for (int p = base + threadIdx.x; p < base + PP / 4; p += 256) {
        float v = ious[g_flat[p]];
        u64 key = ((u64)__float_as_uint(v) << 32) | (u64)(0xFFFFFFFFu - (unsigned)p);
        best = best > key ? best : key;
    }
    __shared__ u64 r[256];
    r[threadIdx.x] = best;
    __syncthreads();
    for (int off = 128; off > 0; off >>= 1) {
        if (threadIdx.x < off && r[threadIdx.x + off] > r[threadIdx.x])
            r[threadIdx.x] = r[threadIdx.x + off];
        __syncthreads();
    }
    if (threadIdx.x == 0) atomicMax(&g_best[s], r[0]);
}

// ---------------- kernel 4: inter-query masked neg-exp partials -------------
// grid (32, 64): one block per (video b, sentence s).
__global__ __launch_bounds__(256) void qsum_kernel(const float* __restrict__ iou) {
    const int b = blockIdx.x, s = blockIdx.y;
    const bool isscat = (g_scatter[s] == b);
    const float4* G4 = reinterpret_cast<const float4*>(g_G + (size_t)s * BP + b * PP);
    const float4* R4 = reinterpret_cast<const float4*>(g_rnormC + b * PP);
    const int4*   F4 = reinterpret_cast<const int4*>(g_flat);
    const float* ious = iou + s * NSQ;

    float acc = 0.0f;
    for (int i = threadIdx.x; i < PP / 4; i += 256) {
        float4 g = G4[i], rn = R4[i];
        float e0 = fexp2(g.x * rn.x);
        float e1 = fexp2(g.y * rn.y);
        float e2 = fexp2(g.z * rn.z);
        float e3 = fexp2(g.w * rn.w);
        if (isscat) {
            int4 f = F4[i];
            if (ious[f.x] > 0.5f) e0 = 0.0f;
            if (ious[f.y] > 0.5f) e1 = 0.0f;
            if (ious[f.z] > 0.5f) e2 = 0.0f;
            if (ious[f.w] > 0.5f) e3 = 0.0f;
        }
        acc += (e0 + e1) + (e2 + e3);
    }
    __shared__ float r[256];
    r[threadIdx.x] = acc;
    __syncthreads();
    for (int off = 128; off > 0; off >>= 1) {
        if (threadIdx.x < off) r[threadIdx.x] += r[threadIdx.x + off];
        __syncthreads();
    }
    if (threadIdx.x == 0) g_qpart[s * BB + b] = r[0];
}

// ---------------- kernel 5: assemble both losses ----------------------------
__global__ void final_kernel(float* __restrict__ out) {
    const int s = threadIdx.x;   // 64 threads
    const int p = (int)(0xFFFFFFFFu - (unsigned)(g_best[s] & 0xFFFFFFFFull));
    const int col = g_scatter[s] * PP + p;
    const float rn = g_rnormC[col];

    const float tpos  = g_G[(size_t)s * BP + col] * rn;   // pos/T * log2e
    const float pos10 = tpos * LN2;                       // pos/T
    const float pe    = fexp2(tpos);

    float nv = 0.0f;                                      // inter-video negs
    for (int t2 = 0; t2 < SS; t2++)
        if (t2 != s) nv += fexp2(g_G[(size_t)t2 * BP + col] * rn);

    float qs = 0.0f;                                      // inter-query negs
    #pragma unroll
    for (int b = 0; b < BB; b++) qs += g_qpart[s * BB + b];

    const float lv = logf(pe + nv) - pos10;
    const float lq = logf(pe + qs) - pos10;

    __shared__ float sv[64], sq[64];
    sv[s] = lv; sq[s] = lq;
    __syncthreads();
    for (int off = 32; off > 0; off >>= 1) {
        if (s < off) { sv[s] += sv[s + off]; sq[s] += sq[s + off]; }
        __syncthreads();
    }
    if (s == 0) {
        out[0] = sv[0] * (1.0f / SS);
        out[1] = sq[0] * (1.0f / SS);
    }
}

// ---------------- launch ----------------------------------------------------
extern "C" void kernel_launch(void* const* d_in, const int* in_sizes, int n_in,
                              void* d_out, int out_size) {
    (void)in_sizes; (void)n_in; (void)out_size;
    const float* video = (const float*)d_in[0];   // [B,C,N,N] f32
    const float* sents = (const float*)d_in[1];   // [S,C] f32
    const int*   ntgt  = (const int*)d_in[2];     // [B] i32
    const float* iou   = (const float*)d_in[3];   // [S,N,N] f32
    // d_in[4] = mask2d (structural triu, hardcoded)
    float* out = (float*)d_out;

    setup_kernel<<<SS, 256>>>(sents, ntgt);
    gemm_kernel<<<dim3(PP / 32, BB), 256>>>(video);
    topk_kernel<<<dim3(4, SS), 256>>>(iou);
    qsum_kernel<<<dim3(BB, SS), 256>>>(iou);
    final_kernel<<<1, SS>>>(out);
}

// round 14
// speedup vs baseline: 1.6524x; 1.3493x over previous
#include <cuda_runtime.h>
#include <cuda_bf16.h>
#include <math.h>
#include <stdint.h>

// Fixed problem shapes
#define BB   32
#define CC   256
#define NN   64
#define NSQ  4096
#define PP   2080
#define SS   64
#define BP   66560
#define NTILE 64
#define NCTA  (BP / NTILE)        // 1040
#define LOG2E10 14.4269504089f    // 10/T * log2(e), T=0.1
#define LN2     0.69314718056f
#define BPAD 67                   // u32 stride per B column in smem

typedef unsigned long long u64;
typedef unsigned int u32;

// ---------------- scratch ----------------------------------------------------
__device__ int   g_flat[PP];
__device__ int   g_scatter[SS];
__device__ int   g_sbase[BB + 1];
__device__ u32   g_sfh2[SS * 128];     // sentence hi bf16x2 pairs, k-major
__device__ u32   g_sfl2[SS * 128];     // sentence lo bf16x2 pairs
__device__ uint4 g_AF[4 * 16 * 2 * 32];// A fragments [mtile][kstep][hi/lo][lane]
__device__ u64   g_best[SS];
__device__ int   g_colp[SS];           // chosen global column per sentence
__device__ u64   g_excl[BP];           // per-column 64-bit sentence exclusion mask
__device__ float g_rnormC[BP];         // rsqrt(||v||^2) * 10*log2e
__device__ float g_qp[NCTA * SS];      // per-CTA qsum partials
__device__ float g_Gcol[SS * SS];      // [s][t] = dot(sent t, chosen prop of s)

// ---------------- fast exp2 (no MUFU) ---------------------------------------
__device__ __forceinline__ float fexp2(float t) {
    float z = t + 12582912.0f;
    int   i = __float_as_int(z) - 0x4B400000;
    float r = t - (z - 12582912.0f);
    float p = 0.00133335581f;
    p = fmaf(p, r, 0.00961812910f);
    p = fmaf(p, r, 0.05550410866f);
    p = fmaf(p, r, 0.24022650696f);
    p = fmaf(p, r, 0.69314718056f);
    p = fmaf(p, r, 1.0f);
    return __int_as_float(__float_as_int(p) + (i << 23));
}

// ---------------- mma.sync m16n8k16 bf16 (baseline PTX, HMMA pipe) ----------
__device__ __forceinline__ void mma16816(float* d, const uint4& a, u32 b0, u32 b1) {
    asm volatile(
        "mma.sync.aligned.m16n8k16.row.col.f32.bf16.bf16.f32 "
        "{%0,%1,%2,%3}, {%4,%5,%6,%7}, {%8,%9}, {%0,%1,%2,%3};"
        : "+f"(d[0]), "+f"(d[1]), "+f"(d[2]), "+f"(d[3])
        : "r"(a.x), "r"(a.y), "r"(a.z), "r"(a.w), "r"(b0), "r"(b1));
}

// ---------------- kernel 1: setup -------------------------------------------
__global__ void setup_kernel(const float* __restrict__ sents,
                             const int* __restrict__ num_targets) {
    const int s = blockIdx.x, t = threadIdx.x, u = s * 256 + t;

    if (u < PP) {
        int start = 0, row = 0, col = 0;
        for (int i = 0; i < NN; i++) {
            int len = NN - i;
            if (u < start + len) { row = i; col = i + (u - start); break; }
            start += len;
        }
        g_flat[u] = row * NN + col;
    }
    if (u < SS) g_best[u] = 0ULL;
    if (u == 0) {
        int idx = 0;
        g_sbase[0] = 0;
        for (int b = 0; b < BB; b++) {
            int n = num_targets[b];
            for (int k = 0; k < n && idx < SS; k++) g_scatter[idx++] = b;
            g_sbase[b + 1] = idx;
        }
    }

    __shared__ float red[256];
    __shared__ float vns[256];
    float v = sents[s * CC + t];
    red[t] = v * v;
    __syncthreads();
    for (int off = 128; off > 0; off >>= 1) {
        if (t < off) red[t] += red[t + off];
        __syncthreads();
    }
    __shared__ float inv;
    if (t == 0) inv = 1.0f / fmaxf(sqrtf(red[0]), 1e-12f);
    __syncthreads();
    vns[t] = v * inv;
    __syncthreads();
    if (t < 128) {
        float a = vns[2 * t], b = vns[2 * t + 1];
        __nv_bfloat16 ha = __float2bfloat16(a), hb = __float2bfloat16(b);
        __nv_bfloat16 la = __float2bfloat16(a - __bfloat162float(ha));
        __nv_bfloat16 lb = __float2bfloat16(b - __bfloat162float(hb));
        g_sfh2[s * 128 + t] = ((u32)__bfloat16_as_ushort(hb) << 16) | __bfloat16_as_ushort(ha);
        g_sfl2[s * 128 + t] = ((u32)__bfloat16_as_ushort(lb) << 16) | __bfloat16_as_ushort(la);
    }
}

// ---------------- kernel 1b: build A fragments in mma register layout -------
// entry (m, kk, h, lane): a0=(r0,kp) a1=(r0+8,kp) a2=(r0,kp+8) a3=(r0+8,kp+8)
__global__ void afrag_kernel() {
    const int idx = blockIdx.x * 256 + threadIdx.x;   // 16 blocks x 256 = 4096
    const int l  = idx & 31;
    const int h  = (idx >> 5) & 1;
    const int kk = (idx >> 6) & 15;
    const int m  = idx >> 10;
    const u32* src = h ? g_sfl2 : g_sfh2;
    const int r0 = m * 16 + (l >> 2);
    const int kp = kk * 8 + (l & 3);
    uint4 f;
    f.x = src[r0 * 128 + kp];
    f.y = src[(r0 + 8) * 128 + kp];
    f.z = src[r0 * 128 + kp + 4];
    f.w = src[(r0 + 8) * 128 + kp + 4];
    g_AF[idx] = f;
}

// ---------------- kernel 2: argmax iou (packed atomicMax) -------------------
__global__ __launch_bounds__(256) void topk_kernel(const float* __restrict__ iou) {
    const int s = blockIdx.y;
    const int base = blockIdx.x * (PP / 4);
    const float* ious = iou + s * NSQ;
    u64 best = 0ULL;
    for (int p = base + threadIdx.x; p < base + PP / 4; p += 256) {
        float v = ious[g_flat[p]];
        u64 key = ((u64)__float_as_uint(v) << 32) | (u64)(0xFFFFFFFFu - (unsigned)p);
        best = best > key ? best : key;
    }
    __shared__ u64 r[256];
    r[threadIdx.x] = best;
    __syncthreads();
    for (int off = 128; off > 0; off >>= 1) {
        if (threadIdx.x < off && r[threadIdx.x + off] > r[threadIdx.x])
            r[threadIdx.x] = r[threadIdx.x + off];
        __syncthreads();
    }
    if (threadIdx.x == 0) atomicMax(&g_best[s], r[0]);
}

// ---------------- kernel 3: exclusion masks + chosen columns ----------------
__global__ __launch_bounds__(256) void excl_kernel(const float* __restrict__ iou) {
    const int u = blockIdx.x * 256 + threadIdx.x;   // 260*256 = 66560 exactly
    if (blockIdx.x == 0 && threadIdx.x < SS) {
        const int s = threadIdx.x;
        int p = (int)(0xFFFFFFFFu - (u32)(g_best[s] & 0xFFFFFFFFull));
        g_colp[s] = g_scatter[s] * PP + p;
    }
    const int b = u / PP;
    const int p = u - b * PP;
    const int f = g_flat[p];
    u64 m = 0;
    const int s0 = g_sbase[b], s1 = g_sbase[b + 1];
    for (int k = s0; k < s1; k++)
        if (iou[k * NSQ + f] > 0.5f) m |= (1ull << k);
    g_excl[u] = m;
}

// ---------------- kernel 4: HMMA GEMM + fused epilogue ----------------------
// grid 1040 x 256 threads. 64 cols/CTA, 64 sentences, K=256 (2 chunks of 128).
// Warp w: m-tile (w&3) rows, 32-col half (w>>2), 4 n-tiles of 8.
__global__ __launch_bounds__(256) void gemm_mma(const float* __restrict__ video) {
    __shared__ __align__(16) u32 smB[2][NTILE * BPAD];   // [hi/lo][col][64 u32 +pad]
    __shared__ u32   offs[NTILE];
    __shared__ u64   exclS[NTILE];
    __shared__ int   colpS[SS];
    __shared__ float nred[4][NTILE];
    __shared__ float rnS[NTILE];
    __shared__ float qps[4][SS];

    const int tid  = threadIdx.x;
    const int warp = tid >> 5, lane = tid & 31;
    const int colbase = blockIdx.x * NTILE;

    if (tid < NTILE) {
        int col = colbase + tid;
        int b = col / PP, p = col - b * PP;
        offs[tid]  = (u32)(b * (CC * NSQ) + g_flat[p]);
        exclS[tid] = g_excl[col];
    }
    if (tid < SS) colpS[tid] = g_colp[tid];
    __syncthreads();

    const int p_ = tid & 63, q_ = tid >> 6;     // staging: col, k-quarter
    const u32 boff_ = offs[p_];
    float nacc = 0.0f;

    const int mtile = warp & 3, ng = warp >> 2;
    float d[4][4];
    #pragma unroll
    for (int i = 0; i < 4; i++)
        #pragma unroll
        for (int j = 0; j < 4; j++) d[i][j] = 0.0f;

    for (int ch = 0; ch < 2; ch++) {
        // ---- stage B: gather fp32, hi/lo bf16 split, k-major per column ----
        const int c0 = ch * 128 + q_ * 32;
        #pragma unroll 4
        for (int i = 0; i < 32; i += 2) {
            float x0 = video[(size_t)boff_ + (size_t)(c0 + i) * NSQ];
            float x1 = video[(size_t)boff_ + (size_t)(c0 + i + 1) * NSQ];
            nacc = fmaf(x0, x0, nacc);
            nacc = fmaf(x1, x1, nacc);
            __nv_bfloat16 h0 = __float2bfloat16(x0);
            __nv_bfloat16 h1 = __float2bfloat16(x1);
            __nv_bfloat16 l0 = __float2bfloat16(x0 - __bfloat162float(h0));
            __nv_bfloat16 l1 = __float2bfloat16(x1 - __bfloat162float(h1));
            const int ki = q_ * 16 + (i >> 1);        // chunk-local u32 index
            smB[0][p_ * BPAD + ki] = ((u32)__bfloat16_as_ushort(h1) << 16) | __bfloat16_as_ushort(h0);
            smB[1][p_ * BPAD + ki] = ((u32)__bfloat16_as_ushort(l1) << 16) | __bfloat16_as_ushort(l0);
        }
        __syncthreads();

        // ---- MMA: 8 k-steps, 4 n-tiles, 3 passes (hh, lh, hl) ----
        #pragma unroll
        for (int ks = 0; ks < 8; ks++) {
            const int kk = ch * 8 + ks;
            const uint4 ah = g_AF[((mtile * 16 + kk) * 2 + 0) * 32 + lane];
            const uint4 al = g_AF[((mtile * 16 + kk) * 2 + 1) * 32 + lane];
            #pragma unroll
            for (int nt = 0; nt < 4; nt++) {
                const int col = ng * 32 + nt * 8 + (lane >> 2);
                const int bi  = col * BPAD + ks * 8 + (lane & 3);
                u32 bh0 = smB[0][bi], bh1 = smB[0][bi + 4];
                u32 bl0 = smB[1][bi], bl1 = smB[1][bi + 4];
                mma16816(d[nt], ah, bh0, bh1);
                mma16816(d[nt], al, bh0, bh1);
                mma16816(d[nt], ah, bl0, bl1);
            }
        }
        __syncthreads();
    }

    // ---- norms ----
    nred[q_][p_] = nacc;
    __syncthreads();
    if (tid < NTILE) {
        float ssq = (nred[0][tid] + nred[1][tid]) + (nred[2][tid] + nred[3][tid]);
        float rn = rsqrtf(ssq) * LOG2E10;
        rnS[tid] = rn;
        g_rnormC[colbase + tid] = rn;
    }

    // ---- write D to smem (reuse B region) ----
    float* Dsm = (float*)smB;                    // [64][65]
    {
        const int r0 = mtile * 16 + (lane >> 2);
        #pragma unroll
        for (int nt = 0; nt < 4; nt++) {
            const int c = ng * 32 + nt * 8 + (lane & 3) * 2;
            Dsm[r0 * 65 + c]           = d[nt][0];
            Dsm[r0 * 65 + c + 1]       = d[nt][1];
            Dsm[(r0 + 8) * 65 + c]     = d[nt][2];
            Dsm[(r0 + 8) * 65 + c + 1] = d[nt][3];
        }
    }
    __syncthreads();

    // ---- masked exp sum: thread owns (s = tid&63, 16 cols) ----
    {
        const int s_ = tid & 63, qq = tid >> 6;
        float acc = 0.0f;
        #pragma unroll
        for (int j = 0; j < 16; j++) {
            const int cl = qq * 16 + j;
            float e = fexp2(Dsm[s_ * 65 + cl] * rnS[cl]);
            if ((exclS[cl] >> s_) & 1ull) e = 0.0f;
            acc += e;
        }
        qps[qq][s_] = acc;
    }
    __syncthreads();
    if (tid < SS) {
        g_qp[blockIdx.x * SS + tid] =
            (qps[0][tid] + qps[1][tid]) + (qps[2][tid] + qps[3][tid]);
        for (int s2 = 0; s2 < SS; s2++) {        // chosen-column extraction
            int c = colpS[s2] - colbase;
            if (c >= 0 && c < NTILE)
                g_Gcol[s2 * SS + tid] = Dsm[tid * 65 + c];
        }
    }
}

// ---------------- kernel 5: assemble losses ---------------------------------
__global__ void final_kernel(float* __restrict__ out) {
    __shared__ float qps[4][SS];
    __shared__ float sv[SS], sq[SS];
    const int t = threadIdx.x;           // 256 threads
    const int s = t & 63, q = t >> 6;

    float part = 0.0f;
    for (int c = q; c < NCTA; c += 4) part += g_qp[c * SS + s];
    qps[q][s] = part;
    __syncthreads();

    if (t < SS) {
        float qs = (qps[0][s] + qps[1][s]) + (qps[2][s] + qps[3][s]);
        const int col = g_colp[s];
        const float rn = g_rnormC[col];
        const float tpos  = g_Gcol[s * SS + s] * rn;
        const float pos10 = tpos * LN2;
        const float pe    = fexp2(tpos);
        float nv = 0.0f;
        for (int t2 = 0; t2 < SS; t2++)
            if (t2 != s) nv += fexp2(g_Gcol[s * SS + t2] * rn);
        sv[s] = logf(pe + nv) - pos10;
        sq[s] = logf(pe + qs) - pos10;
    }
    __syncthreads();
    for (int off = 32; off > 0; off >>= 1) {
        if (t < off) { sv[t] += sv[t + off]; sq[t] += sq[t + off]; }
        __syncthreads();
    }
    if (t == 0) {
        out[0] = sv[0] * (1.0f / SS);
        out[1] = sq[0] * (1.0f / SS);
    }
}

// ---------------- launch ----------------------------------------------------
extern "C" void kernel_launch(void* const* d_in, const int* in_sizes, int n_in,
                              void* d_out, int out_size) {
    (void)in_sizes; (void)n_in; (void)out_size;
    const float* video = (const float*)d_in[0];
    const float* sents = (const float*)d_in[1];
    const int*   ntgt  = (const int*)d_in[2];
    const float* iou   = (const float*)d_in[3];
    float* out = (float*)d_out;

    setup_kernel<<<SS, 256>>>(sents, ntgt);
    afrag_kernel<<<16, 256>>>();
    topk_kernel<<<dim3(4, SS), 256>>>(iou);
    excl_kernel<<<BP / 256, 256>>>(iou);
    gemm_mma<<<NCTA, 256>>>(video);
    final_kernel<<<1, 256>>>(out);
}

// round 16
// speedup vs baseline: 2.0243x; 1.2251x over previous
#include <cuda_runtime.h>
#include <cuda_bf16.h>
#include <math.h>
#include <stdint.h>

// Fixed problem shapes
#define BB   32
#define CC   256
#define NN   64
#define NSQ  4096
#define PP   2080
#define SS   64
#define BP   66560
#define NTILE 64
#define NCTA  (BP / NTILE)        // 1040
#define LOG2E10 14.4269504089f    // 10/T * log2(e), T=0.1
#define LN2     0.69314718056f
#define BPAD 67                   // u32 stride per B column in smem

typedef unsigned long long u64;
typedef unsigned int u32;

// ---------------- scratch ----------------------------------------------------
__device__ int   g_flat[PP];
__device__ int   g_scatter[SS];
__device__ int   g_sbase[BB + 1];
__device__ u32   g_sfh2[SS * 128];     // sentence hi bf16x2 pairs, k-major
__device__ u32   g_sfl2[SS * 128];     // sentence lo bf16x2 pairs
__device__ uint4 g_AF[4 * 16 * 2 * 32];// A fragments [mtile][kstep][hi/lo][lane]
__device__ u64   g_best[SS];
__device__ float g_rnormC[BP];         // rsqrt(||v||^2) * 10*log2e
__device__ float g_qp[SS * NCTA];      // per-(s, CTA) qsum partials, [s][c]
__device__ float g_Gcol[SS * SS];      // [s][t] = dot(sent t, chosen prop of s)

// ---------------- fast exp2 (no MUFU) ---------------------------------------
__device__ __forceinline__ float fexp2(float t) {
    float z = t + 12582912.0f;
    int   i = __float_as_int(z) - 0x4B400000;
    float r = t - (z - 12582912.0f);
    float p = 0.00133335581f;
    p = fmaf(p, r, 0.00961812910f);
    p = fmaf(p, r, 0.05550410866f);
    p = fmaf(p, r, 0.24022650696f);
    p = fmaf(p, r, 0.69314718056f);
    p = fmaf(p, r, 1.0f);
    return __int_as_float(__float_as_int(p) + (i << 23));
}

// ---------------- mma.sync m16n8k16 bf16 (baseline PTX, HMMA pipe) ----------
__device__ __forceinline__ void mma16816(float* d, const uint4& a, u32 b0, u32 b1) {
    asm volatile(
        "mma.sync.aligned.m16n8k16.row.col.f32.bf16.bf16.f32 "
        "{%0,%1,%2,%3}, {%4,%5,%6,%7}, {%8,%9}, {%0,%1,%2,%3};"
        : "+f"(d[0]), "+f"(d[1]), "+f"(d[2]), "+f"(d[3])
        : "r"(a.x), "r"(a.y), "r"(a.z), "r"(a.w), "r"(b0), "r"(b1));
}

// pack two fp32 -> bf16x2 (RN)
__device__ __forceinline__ u32 pack_bf16x2(float lo, float hi) {
    u32 r;
    asm("cvt.rn.bf16x2.f32 %0, %1, %2;" : "=r"(r) : "f"(hi), "f"(lo));
    return r;
}

// ---------------- kernel 1: setup -------------------------------------------
__global__ void setup_kernel(const float* __restrict__ sents,
                             const int* __restrict__ num_targets) {
    const int s = blockIdx.x, t = threadIdx.x, u = s * 256 + t;

    if (u < PP) {
        int start = 0, row = 0, col = 0;
        for (int i = 0; i < NN; i++) {
            int len = NN - i;
            if (u < start + len) { row = i; col = i + (u - start); break; }
            start += len;
        }
        g_flat[u] = row * NN + col;
    }
    if (u < SS) g_best[u] = 0ULL;
    if (u == 0) {
        int idx = 0;
        g_sbase[0] = 0;
        for (int b = 0; b < BB; b++) {
            int n = num_targets[b];
            for (int k = 0; k < n && idx < SS; k++) g_scatter[idx++] = b;
            g_sbase[b + 1] = idx;
        }
    }

    __shared__ float red[256];
    __shared__ float vns[256];
    float v = sents[s * CC + t];
    red[t] = v * v;
    __syncthreads();
    for (int off = 128; off > 0; off >>= 1) {
        if (t < off) red[t] += red[t + off];
        __syncthreads();
    }
    __shared__ float inv;
    if (t == 0) inv = 1.0f / fmaxf(sqrtf(red[0]), 1e-12f);
    __syncthreads();
    vns[t] = v * inv;
    __syncthreads();
    if (t < 128) {
        float a = vns[2 * t], b = vns[2 * t + 1];
        __nv_bfloat16 ha = __float2bfloat16(a), hb = __float2bfloat16(b);
        __nv_bfloat16 la = __float2bfloat16(a - __bfloat162float(ha));
        __nv_bfloat16 lb = __float2bfloat16(b - __bfloat162float(hb));
        g_sfh2[s * 128 + t] = ((u32)__bfloat16_as_ushort(hb) << 16) | __bfloat16_as_ushort(ha);
        g_sfl2[s * 128 + t] = ((u32)__bfloat16_as_ushort(lb) << 16) | __bfloat16_as_ushort(la);
    }
}

// ---------------- kernel 1b: build A fragments in mma register layout -------
__global__ void afrag_kernel() {
    const int idx = blockIdx.x * 256 + threadIdx.x;   // 16 x 256 = 4096
    const int l  = idx & 31;
    const int h  = (idx >> 5) & 1;
    const int kk = (idx >> 6) & 15;
    const int m  = idx >> 10;
    const u32* src = h ? g_sfl2 : g_sfh2;
    const int r0 = m * 16 + (l >> 2);
    const int kp = kk * 8 + (l & 3);
    uint4 f;
    f.x = src[r0 * 128 + kp];
    f.y = src[(r0 + 8) * 128 + kp];
    f.z = src[r0 * 128 + kp + 4];
    f.w = src[(r0 + 8) * 128 + kp + 4];
    g_AF[idx] = f;
}

// ---------------- kernel 2: argmax iou (packed atomicMax) -------------------
__global__ __launch_bounds__(256) void topk_kernel(const float* __restrict__ iou) {
    const int s = blockIdx.y;
    const int base = blockIdx.x * (PP / 4);
    const float* ious = iou + s * NSQ;
    u64 best = 0ULL;
    for (int p = base + threadIdx.x; p < base + PP / 4; p += 256) {
        float v = ious[g_flat[p]];
        u64 key = ((u64)__float_as_uint(v) << 32) | (u64)(0xFFFFFFFFu - (unsigned)p);
        best = best > key ? best : key;
    }
    __shared__ u64 r[256];
    r[threadIdx.x] = best;
    __syncthreads();
    for (int off = 128; off > 0; off >>= 1) {
        if (threadIdx.x < off && r[threadIdx.x + off] > r[threadIdx.x])
            r[threadIdx.x] = r[threadIdx.x + off];
        __syncthreads();
    }
    if (threadIdx.x == 0) atomicMax(&g_best[s], r[0]);
}

// ---------------- kernel 3: HMMA GEMM + fused epilogue (mask inline) --------
// grid 1040 x 256 threads. 64 cols/CTA, 64 sentences, K=256 (2 chunks of 128).
__global__ __launch_bounds__(256) void gemm_mma(const float* __restrict__ video,
                                                const float* __restrict__ iou) {
    __shared__ __align__(16) u32 smB[2][NTILE * BPAD];   // [hi/lo][col][64 u32 +pad]
    __shared__ u32   offs[NTILE];
    __shared__ int   flatS[NTILE];
    __shared__ u64   exclS[NTILE];
    __shared__ int   colpS[SS];
    __shared__ float nred[4][NTILE];
    __shared__ float rnS[NTILE];
    __shared__ float qps[4][SS];

    const int tid  = threadIdx.x;
    const int warp = tid >> 5, lane = tid & 31;
    const int colbase = blockIdx.x * NTILE;

    if (tid < NTILE) {
        int col = colbase + tid;
        int b = col / PP, p = col - b * PP;
        int f = g_flat[p];
        flatS[tid] = f;
        offs[tid]  = (u32)(b * (CC * NSQ) + f);
    }
    if (tid < SS) {
        u64 bst = g_best[tid];
        int p = (int)(0xFFFFFFFFu - (u32)(bst & 0xFFFFFFFFull));
        colpS[tid] = g_scatter[tid] * PP + p;
    }
    __syncthreads();

    const int p_ = tid & 63, q_ = tid >> 6;     // staging: col, k-quarter
    const u32 boff_ = offs[p_];
    float nacc = 0.0f;

    const int mtile = warp & 3, ng = warp >> 2;
    float d[4][4];
    #pragma unroll
    for (int i = 0; i < 4; i++)
        #pragma unroll
        for (int j = 0; j < 4; j++) d[i][j] = 0.0f;

    for (int ch = 0; ch < 2; ch++) {
        // ---- stage B: batched gather, hi/lo bf16 split, k-major per column ----
        const int c0 = ch * 128 + q_ * 32;
        #pragma unroll
        for (int half = 0; half < 2; half++) {
            float x[16];
            #pragma unroll
            for (int i = 0; i < 16; i++)
                x[i] = video[(size_t)boff_ + (size_t)(c0 + half * 16 + i) * NSQ];
            #pragma unroll
            for (int i = 0; i < 16; i += 2) {
                float x0 = x[i], x1 = x[i + 1];
                nacc = fmaf(x0, x0, nacc);
                nacc = fmaf(x1, x1, nacc);
                u32 hp = pack_bf16x2(x0, x1);
                float h0 = __int_as_float(hp << 16);
                float h1 = __int_as_float(hp & 0xFFFF0000u);
                u32 lp = pack_bf16x2(x0 - h0, x1 - h1);
                const int ki = q_ * 16 + ((half * 16 + i) >> 1);
                smB[0][p_ * BPAD + ki] = hp;
                smB[1][p_ * BPAD + ki] = lp;
            }
        }
        __syncthreads();

        // ---- MMA: 8 k-steps, 4 n-tiles, 3 passes (hh, lh, hl) ----
        #pragma unroll
        for (int ks = 0; ks < 8; ks++) {
            const int kk = ch * 8 + ks;
            const uint4 ah = g_AF[((mtile * 16 + kk) * 2 + 0) * 32 + lane];
            const uint4 al = g_AF[((mtile * 16 + kk) * 2 + 1) * 32 + lane];
            #pragma unroll
            for (int nt = 0; nt < 4; nt++) {
                const int col = ng * 32 + nt * 8 + (lane >> 2);
                const int bi  = col * BPAD + ks * 8 + (lane & 3);
                u32 bh0 = smB[0][bi], bh1 = smB[0][bi + 4];
                u32 bl0 = smB[1][bi], bl1 = smB[1][bi + 4];
                mma16816(d[nt], ah, bh0, bh1);
                mma16816(d[nt], al, bh0, bh1);
                mma16816(d[nt], ah, bl0, bl1);
            }
        }
        __syncthreads();
    }

    // ---- inline iou exclusion mask (overlaps norm reduction) ----
    u64 m_ = 0;
    if (tid < NTILE) {
        int col = colbase + tid;
        int b = col / PP;
        int f = flatS[tid];
        int s0 = g_sbase[b], s1 = g_sbase[b + 1];
        for (int k = s0; k < s1; k++)
            if (iou[k * NSQ + f] > 0.5f) m_ |= (1ull << k);
    }

    // ---- norms ----
    nred[q_][p_] = nacc;
    __syncthreads();
    if (tid < NTILE) {
        float ssq = (nred[0][tid] + nred[1][tid]) + (nred[2][tid] + nred[3][tid]);
        float rn = rsqrtf(ssq) * LOG2E10;
        rnS[tid] = rn;
        exclS[tid] = m_;
        g_rnormC[colbase + tid] = rn;
    }

    // ---- write D to smem (reuse B region) ----
    float* Dsm = (float*)smB;                    // [64][65]
    {
        const int r0 = mtile * 16 + (lane >> 2);
        #pragma unroll
        for (int nt = 0; nt < 4; nt++) {
            const int c = ng * 32 + nt * 8 + (lane & 3) * 2;
            Dsm[r0 * 65 + c]           = d[nt][0];
            Dsm[r0 * 65 + c + 1]       = d[nt][1];
            Dsm[(r0 + 8) * 65 + c]     = d[nt][2];
            Dsm[(r0 + 8) * 65 + c + 1] = d[nt][3];
        }
    }
    __syncthreads();

    // ---- masked exp sum: thread owns (s = tid&63, 16 cols) ----
    {
        const int s_ = tid & 63, qq = tid >> 6;
        float acc = 0.0f;
        #pragma unroll
        for (int j = 0; j < 16; j++) {
            const int cl = qq * 16 + j;
            float e = fexp2(Dsm[s_ * 65 + cl] * rnS[cl]);
            if ((exclS[cl] >> s_) & 1ull) e = 0.0f;
            acc += e;
        }
        qps[qq][s_] = acc;
    }
    __syncthreads();
    if (tid < SS) {
        g_qp[tid * NCTA + blockIdx.x] =
            (qps[0][tid] + qps[1][tid]) + (qps[2][tid] + qps[3][tid]);
        for (int s2 = 0; s2 < SS; s2++) {        // chosen-column extraction
            int c = colpS[s2] - colbase;
            if (c >= 0 && c < NTILE)
                g_Gcol[s2 * SS + tid] = Dsm[tid * 65 + c];
        }
    }
}

// ---------------- kernel 4: qp reduction + loss assembly --------------------
__global__ __launch_bounds__(1024) void final_kernel(float* __restrict__ out) {
    __shared__ float redq[SS][17];
    __shared__ float sv[SS], sq[SS];
    const int t = threadIdx.x;           // 1024 threads
    const int s = t >> 4, j = t & 15;

    float part = 0.0f;
    for (int c = j; c < NCTA; c += 16) part += g_qp[s * NCTA + c];
    redq[s][j] = part;
    __syncthreads();

    if (t < SS) {
        float qs = 0.0f;
        #pragma unroll
        for (int k = 0; k < 16; k++) qs += redq[t][k];

        u64 bst = g_best[t];
        int p = (int)(0xFFFFFFFFu - (u32)(bst & 0xFFFFFFFFull));
        const int col = g_scatter[t] * PP + p;
        const float rn = g_rnormC[col];
        const float tpos  = g_Gcol[t * SS + t] * rn;
        const float pos10 = tpos * LN2;
        const float pe    = fexp2(tpos);
        float nv = 0.0f;
        for (int t2 = 0; t2 < SS; t2++)
            if (t2 != t) nv += fexp2(g_Gcol[t * SS + t2] * rn);
        sv[t] = logf(pe + nv) - pos10;
        sq[t] = logf(pe + qs) - pos10;
    }
    __syncthreads();
    for (int off = 32; off > 0; off >>= 1) {
        if (t < off) { sv[t] += sv[t + off]; sq[t] += sq[t + off]; }
        __syncthreads();
    }
    if (t == 0) {
        out[0] = sv[0] * (1.0f / SS);
        out[1] = sq[0] * (1.0f / SS);
    }
}

// ---------------- launch ----------------------------------------------------
extern "C" void kernel_launch(void* const* d_in, const int* in_sizes, int n_in,
                              void* d_out, int out_size) {
    (void)in_sizes; (void)n_in; (void)out_size;
    const float* video = (const float*)d_in[0];
    const float* sents = (const float*)d_in[1];
    const int*   ntgt  = (const int*)d_in[2];
    const float* iou   = (const float*)d_in[3];
    float* out = (float*)d_out;

    setup_kernel<<<SS, 256>>>(sents, ntgt);
    afrag_kernel<<<16, 256>>>();
    topk_kernel<<<dim3(4, SS), 256>>>(iou);
    gemm_mma<<<NCTA, 256>>>(video, iou);
    final_kernel<<<1, 1024>>>(out);
}